// round 2
// baseline (speedup 1.0000x reference)
#include <cuda_runtime.h>

// CrossAttentionConditionInjection — analytic collapse.
//
// K/V come from a single condition token broadcast across seq: every score row
// is constant => softmax weights are exactly 1/S (S=2048, power of two)
// => attn == v1 broadcast. Entire op:
//   out[b,s,:] = Wo @ (Wv @ cond[b] + bv) + bo     (same vector for every s)
//
// R2 change vs R1: matvecs were latency-bound (occ 22%, DRAM 9%). Now each
// (b,d) dot is split across 4 warps (quarter-row each, 2 float4/thread),
// combined in smem. 4x threads, 4x shorter per-warp critical path.

#define BDIM 1024   // D
#define NB   2      // B
#define NS   2048   // S

__device__ float g_v1[NB * BDIM];
__device__ float g_o1[NB * BDIM];

// ---------------------------------------------------------------------------
// Shared matvec body. 256 threads/block = 2 tasks; each task (b,d) is one
// 128-thread group: 4 warps x quarter-row (256 floats) x (2 float4 / lane).
// Grid = 1024 blocks covers 2048 tasks.
// ---------------------------------------------------------------------------
__device__ __forceinline__ void mv_body(const float* __restrict__ W,
                                        const float* __restrict__ x,   // [NB][BDIM]
                                        const float* __restrict__ bias,
                                        float* __restrict__ y) {       // [NB*BDIM]
    __shared__ float red[8];                       // 2 tasks x 4 warps

    int sub  = threadIdx.x >> 7;                   // task within block (0/1)
    int t    = blockIdx.x * 2 + sub;               // global task 0..2047
    int b    = t >> 10;
    int d    = t & (BDIM - 1);
    int q    = (threadIdx.x >> 5) & 3;             // quarter-row
    int lane = threadIdx.x & 31;

    // float4 indices: quarter q covers float4 [q*64, q*64+64)
    int iw = d * (BDIM / 4) + q * 64 + lane;       // W row, float4 units
    int ix = b * (BDIM / 4) + q * 64 + lane;

    const float4* W4 = reinterpret_cast<const float4*>(W);
    const float4* x4 = reinterpret_cast<const float4*>(x);

    float4 a0 = W4[iw];
    float4 a1 = W4[iw + 32];
    float4 c0 = x4[ix];
    float4 c1 = x4[ix + 32];

    float sum = a0.x * c0.x + a0.y * c0.y + a0.z * c0.z + a0.w * c0.w
              + a1.x * c1.x + a1.y * c1.y + a1.z * c1.z + a1.w * c1.w;

#pragma unroll
    for (int off = 16; off; off >>= 1)
        sum += __shfl_xor_sync(0xffffffffu, sum, off);

    if (lane == 0) red[sub * 4 + q] = sum;
    __syncthreads();

    if ((threadIdx.x & 127) == 0) {
        float r = red[sub * 4 + 0] + red[sub * 4 + 1]
                + red[sub * 4 + 2] + red[sub * 4 + 3];
        y[t] = r + bias[d];
    }
}

__global__ void __launch_bounds__(256) mv_stage1(const float* __restrict__ Wv,
                                                 const float* __restrict__ cond,
                                                 const float* __restrict__ bv) {
    mv_body(Wv, cond, bv, g_v1);
}

__global__ void __launch_bounds__(256) mv_stage2(const float* __restrict__ Wo,
                                                 const float* __restrict__ bo) {
    mv_body(Wo, g_v1, bo, g_o1);
}

// ---------------------------------------------------------------------------
// Broadcast: out[b,s,d] = g_o1[b,d]. Pure coalesced float4 stores; the 8 KB
// source stays hot in L1/L2. One float4 store per thread.
// ---------------------------------------------------------------------------
__global__ void __launch_bounds__(512) bcast_kernel(float4* __restrict__ out) {
    const float4* o1 = reinterpret_cast<const float4*>(g_o1);
    int i  = blockIdx.x * blockDim.x + threadIdx.x;
    int b  = i >> 19;          // / (S*D/4)
    int d4 = i & 255;          // % (D/4)
    out[i] = o1[(b << 8) + d4];
}

extern "C" void kernel_launch(void* const* d_in, const int* in_sizes, int n_in,
                              void* d_out, int out_size) {
    // metadata order: hidden_states, condition, Wq, bq, Wk, bk, Wv, bv, Wo, bo
    const float* cond = (const float*)d_in[1];
    const float* Wv   = (const float*)d_in[6];
    const float* bv   = (const float*)d_in[7];
    const float* Wo   = (const float*)d_in[8];
    const float* bo   = (const float*)d_in[9];
    float*       out  = (float*)d_out;

    mv_stage1<<<1024, 256>>>(Wv, cond, bv);
    mv_stage2<<<1024, 256>>>(Wo, bo);
    bcast_kernel<<<(NB * NS * BDIM / 4) / 512, 512>>>((float4*)out);
}